// round 15
// baseline (speedup 1.0000x reference)
#include <cuda_runtime.h>
#include <cuda_bf16.h>
#include <cstdint>
#include <math.h>

// NT-Xent loss, B=4096, D=128, N=8192, T=0.5 — mma.sync bf16, SYMMETRIC v3
// R15: ONE persistent kernel (148 blocks = 1 wave), spin barriers between
// norm / sim / finish phases; serpentine strip-contiguous chunks of 14-15
// tiles; exp affine folded into stored data (term = ex2(dot')).

#define NB   4096
#define NN   8192
#define NT   2080
#define NBLK 148
#define C1   2.8853900817779268f   // 2*log2(e)
#define SC   1.69864364f           // sqrt(C1)
#define LN2  0.69314718055994531f

__device__ __align__(16) unsigned char g_Zb[NN * 256];  // bf16 rows (scaled)
__device__ float g_rowsum[NN];
__device__ float g_self[NN];
__device__ float g_loss;
__device__ unsigned int g_bar1, g_bar2, g_done;

// ---------- helpers ----------
static __device__ __forceinline__ uint32_t smem_u32(const void* p) {
    uint32_t a;
    asm("{ .reg .u64 t; cvta.to.shared.u64 t, %1; cvt.u32.u64 %0, t; }"
        : "=r"(a) : "l"(p));
    return a;
}
#define CP_ASYNC16(dst, src) \
    asm volatile("cp.async.cg.shared.global [%0], [%1], 16;" :: "r"(dst), "l"(src))
#define CP_COMMIT() asm volatile("cp.async.commit_group;")
#define CP_WAIT(n)  asm volatile("cp.async.wait_group %0;" :: "n"(n))

static __device__ __forceinline__ void ldm_x4(uint32_t& r0, uint32_t& r1,
                                              uint32_t& r2, uint32_t& r3,
                                              uint32_t addr) {
    asm volatile("ldmatrix.sync.aligned.m8n8.x4.shared.b16 {%0,%1,%2,%3}, [%4];"
                 : "=r"(r0), "=r"(r1), "=r"(r2), "=r"(r3) : "r"(addr));
}
static __device__ __forceinline__ void mma16816(float* c, const uint32_t* a,
                                                const uint32_t* b) {
    asm volatile(
        "mma.sync.aligned.m16n8k16.row.col.f32.bf16.bf16.f32 "
        "{%0,%1,%2,%3}, {%4,%5,%6,%7}, {%8,%9}, {%0,%1,%2,%3};"
        : "+f"(c[0]), "+f"(c[1]), "+f"(c[2]), "+f"(c[3])
        : "r"(a[0]), "r"(a[1]), "r"(a[2]), "r"(a[3]), "r"(b[0]), "r"(b[1]));
}
static __device__ __forceinline__ float ex2f(float x) {
    float r;
    asm("ex2.approx.f32 %0, %1;" : "=f"(r) : "f"(x));
    return r;
}

// spin barrier: tid0 arrives + polls, block releases via __syncthreads
static __device__ __forceinline__ void grid_bar(unsigned int* ctr, int tid) {
    __threadfence();
    __syncthreads();
    if (tid == 0) {
        atomicAdd(ctr, 1u);
        while (*(volatile unsigned int*)ctr < NBLK) __nanosleep(64);
    }
    __syncthreads();
    __threadfence();
}

// serpentine strip order: pairs (r=p len 64-p, r=63-p len p+1), 65 tiles/pair
static __device__ __forceinline__ void decode(int q, int& r, int& c) {
    int p = q / 65;
    int off = q - p * 65;
    int len1 = 64 - p;
    if (off < len1) { r = p; c = p + off; }
    else            { r = 63 - p; c = r + (off - len1); }
}

static __device__ __forceinline__ void stageP(uint32_t dst, int panel, int tid) {
    const unsigned char* Z = g_Zb;
    #pragma unroll
    for (int i = 0; i < 8; i++) {
        int idx = tid + i * 256;
        int row = idx >> 4, ch = idx & 15;
        uint32_t off = (uint32_t)(row * 256 + ((ch ^ (row & 7)) * 16));
        CP_ASYNC16(dst + off, Z + (size_t)(panel * 128 + row) * 256 + ch * 16);
    }
}

template <bool DRAIN>
static __device__ __forceinline__ void mma_half(
    float* __restrict__ acc, float* __restrict__ epi,
    float* __restrict__ rowacc, float* __restrict__ colacc,
    uint32_t buf, int ncol0, int n_loc, int cpar, const uint32_t (*Ar)[8][4])
{
    #pragma unroll
    for (int f = 0; f < 32; f++) acc[f] = 0.f;
    #pragma unroll
    for (int ks = 0; ks < 8; ks++) {
        uint32_t bfr[8];
        #pragma unroll
        for (int pr = 0; pr < 2; pr++) {
            int n = ncol0 + pr * 16 + n_loc;
            uint32_t addr = buf + (uint32_t)n * 256u
                          + (uint32_t)(((2 * ks + cpar) ^ (n_loc & 7)) * 16);
            ldm_x4(bfr[pr*4+0], bfr[pr*4+1], bfr[pr*4+2], bfr[pr*4+3], addr);
        }
        #pragma unroll
        for (int mi = 0; mi < 2; mi++) {
            mma16816(&acc[mi*16 + 0],  Ar[mi][ks], &bfr[0]);
            mma16816(&acc[mi*16 + 4],  Ar[mi][ks], &bfr[2]);
            mma16816(&acc[mi*16 + 8],  Ar[mi][ks], &bfr[4]);
            mma16816(&acc[mi*16 + 12], Ar[mi][ks], &bfr[6]);
        }
        if (DRAIN) {
            #pragma unroll
            for (int u = 0; u < 4; u++) {
                int f = ks * 4 + u;
                float e = ex2f(epi[f]);
                rowacc[((f >> 4) << 1) | ((f & 3) >> 1)] += e;
                colacc[(((f >> 2) & 3) << 1) | (f & 1)] += e;
            }
        }
    }
}

static __device__ __forceinline__ void drain32(
    const float* __restrict__ epi, float* __restrict__ rowacc,
    float* __restrict__ colacc)
{
    #pragma unroll
    for (int f = 0; f < 32; f++) {
        float e = ex2f(epi[f]);
        rowacc[((f >> 4) << 1) | ((f & 3) >> 1)] += e;
        colacc[(((f >> 2) & 3) << 1) | (f & 1)] += e;
    }
}

static __device__ __forceinline__ void colflush(float* __restrict__ colacc,
                                                int colbase, int lane) {
    #pragma unroll
    for (int q = 0; q < 8; q++) {
        colacc[q] += __shfl_xor_sync(0xffffffffu, colacc[q], 4);
        colacc[q] += __shfl_xor_sync(0xffffffffu, colacc[q], 8);
        colacc[q] += __shfl_xor_sync(0xffffffffu, colacc[q], 16);
    }
    if (lane < 4) {
        #pragma unroll
        for (int q = 0; q < 8; q++) {
            int col = colbase + (q >> 1) * 8 + 2 * lane + (q & 1);
            atomicAdd(&g_rowsum[col], colacc[q]);
        }
    }
}

// ---------- the one kernel ----------
__global__ void __launch_bounds__(256, 1) fused_kernel(
    const float* __restrict__ zi, const float* __restrict__ zj,
    float* __restrict__ out)
{
    extern __shared__ unsigned char smraw[];
    uint32_t s0 = smem_u32(smraw);
    uint32_t Abuf[2] = { s0, s0 + 32768u };
    uint32_t Bbuf[2] = { s0 + 65536u, s0 + 98304u };

    int tid = threadIdx.x, lane = tid & 31, w = tid >> 5;
    int b = blockIdx.x;

    // ---- phase 0: zero rowsum + normalize ----
    for (int gt = b * 256 + tid; gt < NN; gt += NBLK * 256)
        g_rowsum[gt] = 0.f;
    int gwid = b * 8 + w;                        // 0..1183
    for (int row = gwid; row < NN; row += NBLK * 8) {
        const float* src = (row < NB) ? (zi + (size_t)row * 128)
                                      : (zj + (size_t)(row - NB) * 128);
        float4 v = ((const float4*)src)[lane];
        float ss = v.x*v.x + v.y*v.y + v.z*v.z + v.w*v.w;
        #pragma unroll
        for (int o = 16; o; o >>= 1) ss += __shfl_xor_sync(0xffffffffu, ss, o);
        float sca = SC / fmaxf(sqrtf(ss), 1e-12f);
        __nv_bfloat162 p0 = __floats2bfloat162_rn(v.x * sca, v.y * sca);
        __nv_bfloat162 p1 = __floats2bfloat162_rn(v.z * sca, v.w * sca);
        float2 q0 = __bfloat1622float2(p0);
        float2 q1 = __bfloat1622float2(p1);
        float sd = q0.x*q0.x + q0.y*q0.y + q1.x*q1.x + q1.y*q1.y;
        #pragma unroll
        for (int o = 16; o; o >>= 1) sd += __shfl_xor_sync(0xffffffffu, sd, o);
        if (lane == 0) g_self[row] = sd;
        uint2 pk;
        pk.x = *reinterpret_cast<uint32_t*>(&p0);
        pk.y = *reinterpret_cast<uint32_t*>(&p1);
        *reinterpret_cast<uint2*>(g_Zb + (size_t)row * 256 + lane * 8) = pk;
    }
    grid_bar(&g_bar1, tid);

    // ---- phase 1: symmetric sim sweep ----
    int wm = w & 3, wn = w >> 2;
    int cnt = 14 + (b < 8 ? 1 : 0);
    int q0 = b * 14 + (b < 8 ? b : 8);

    int n_loc = (lane & 7) + ((lane >> 4) << 3);
    int cpar = (lane >> 3) & 1;
    int row_loc = (lane & 7) + ((lane >> 3) & 1) * 8;
    int kpar = (lane >> 4) & 1;

    int r0p, c0p, r1p, c1p;
    decode(q0, r0p, c0p);
    decode(q0 + 1, r1p, c1p);
    stageP(Abuf[0], r0p, tid);
    stageP(Bbuf[0], c0p, tid);
    CP_COMMIT();
    int stgA = 1;
    if (r1p != r0p) { stageP(Abuf[1], r1p, tid); stgA = 0; }
    stageP(Bbuf[1], c1p, tid);
    CP_COMMIT();

    uint32_t Ar[2][8][4];
    float rowacc[4], colacc[8];
    float accA[32], accB[32];
    int useA = 0, rprev = -1;

    for (int t = 0; t < cnt; t++) {
        int q = q0 + t;
        int r, c;
        decode(q, r, c);
        int buf = t & 1;

        CP_WAIT(1);
        __syncthreads();

        if (r != rprev) {
            if (t > 0) useA ^= 1;
            uint32_t abase = Abuf[useA] + (uint32_t)(wm * 32 + row_loc) * 256u;
            #pragma unroll
            for (int ma = 0; ma < 2; ma++)
                #pragma unroll
                for (int ks = 0; ks < 8; ks++) {
                    uint32_t addr = abase + (uint32_t)(ma * 16) * 256u
                                  + (uint32_t)(((2 * ks + kpar) ^ (row_loc & 7)) * 16);
                    ldm_x4(Ar[ma][ks][0], Ar[ma][ks][1], Ar[ma][ks][2], Ar[ma][ks][3], addr);
                }
        }
        rprev = r;

        #pragma unroll
        for (int k2 = 0; k2 < 4; k2++) rowacc[k2] = 0.f;
        #pragma unroll
        for (int k2 = 0; k2 < 8; k2++) colacc[k2] = 0.f;

        int nbase = wn * 64;
        mma_half<false>(accA, accA, rowacc, colacc, Bbuf[buf], nbase, n_loc, cpar, Ar);
        mma_half<true >(accB, accA, rowacc, colacc, Bbuf[buf], nbase + 32, n_loc, cpar, Ar);
        if (r != c) colflush(colacc, c * 128 + nbase, lane);
        #pragma unroll
        for (int k2 = 0; k2 < 8; k2++) colacc[k2] = 0.f;
        drain32(accB, rowacc, colacc);
        if (r != c) colflush(colacc, c * 128 + nbase + 32, lane);

        #pragma unroll
        for (int k2 = 0; k2 < 4; k2++) {
            rowacc[k2] += __shfl_xor_sync(0xffffffffu, rowacc[k2], 1);
            rowacc[k2] += __shfl_xor_sync(0xffffffffu, rowacc[k2], 2);
        }
        if ((lane & 3) == 0) {
            int rbase = r * 128 + wm * 32 + (lane >> 2);
            atomicAdd(&g_rowsum[rbase],      rowacc[0]);
            atomicAdd(&g_rowsum[rbase + 8],  rowacc[1]);
            atomicAdd(&g_rowsum[rbase + 16], rowacc[2]);
            atomicAdd(&g_rowsum[rbase + 24], rowacc[3]);
        }

        __syncthreads();
        if (t + 2 < cnt) {
            int r2, c2, rn, cn;
            decode(q + 2, r2, c2);
            decode(q + 1, rn, cn);
            stageP(Bbuf[buf], c2, tid);
            if (r2 != rn) { stageP(Abuf[stgA], r2, tid); stgA ^= 1; }
        }
        CP_COMMIT();
    }
    grid_bar(&g_bar2, tid);

    // ---- phase 2: finish (warp per positive pair, strided) ----
    __shared__ float sh[8];
    float wloss = 0.f;
    for (int p = gwid; p < NB; p += NBLK * 8) {
        int qq = p + NB;
        uint2 ua = *reinterpret_cast<const uint2*>(g_Zb + (size_t)p * 256 + lane * 8);
        uint2 ub = *reinterpret_cast<const uint2*>(g_Zb + (size_t)qq * 256 + lane * 8);
        float2 a0 = __bfloat1622float2(*reinterpret_cast<__nv_bfloat162*>(&ua.x));
        float2 a1 = __bfloat1622float2(*reinterpret_cast<__nv_bfloat162*>(&ua.y));
        float2 b0 = __bfloat1622float2(*reinterpret_cast<__nv_bfloat162*>(&ub.x));
        float2 b1 = __bfloat1622float2(*reinterpret_cast<__nv_bfloat162*>(&ub.y));
        float pd = a0.x*b0.x + a0.y*b0.y + a1.x*b1.x + a1.y*b1.y;
        #pragma unroll
        for (int o = 16; o; o >>= 1) pd += __shfl_xor_sync(0xffffffffu, pd, o);
        if (lane == 0) {
            float rsp = __ldcg(&g_rowsum[p])  - ex2f(g_self[p]);
            float rsq = __ldcg(&g_rowsum[qq]) - ex2f(g_self[qq]);
            wloss += logf(rsp) + logf(rsq) - 2.0f * LN2 * pd;
        }
    }
    if (lane == 0) sh[w] = wloss;
    __syncthreads();
    if (tid == 0) {
        float t = 0.f;
        #pragma unroll
        for (int kk = 0; kk < 8; kk++) t += sh[kk];
        atomicAdd(&g_loss, t);
        __threadfence();
        unsigned int done = atomicAdd(&g_done, 1u);
        if (done == NBLK - 1) {                   // last block: write + reset
            out[0] = *(volatile float*)&g_loss * (1.0f / (float)NN);
            g_loss = 0.f;
            g_bar1 = 0u; g_bar2 = 0u; g_done = 0u;
        }
    }
}

extern "C" void kernel_launch(void* const* d_in, const int* in_sizes, int n_in,
                              void* d_out, int out_size) {
    const float* zi = (const float*)d_in[0];
    const float* zj = (const float*)d_in[1];
    float* out = (float*)d_out;
    (void)in_sizes; (void)n_in; (void)out_size;

    (void)cudaFuncSetAttribute(fused_kernel,
                               cudaFuncAttributeMaxDynamicSharedMemorySize,
                               131072);

    fused_kernel<<<NBLK, 256, 131072>>>(zi, zj, out);
}

// round 16
// speedup vs baseline: 1.1086x; 1.1086x over previous
#include <cuda_runtime.h>
#include <cuda_bf16.h>
#include <cstdint>
#include <math.h>

// NT-Xent loss, B=4096, D=128, N=8192, T=0.5 — mma.sync bf16, SYMMETRIC v4
// R16: 3 kernels again (fused-barrier version regressed); sim epilogue fully
// pipelined ACROSS tiles: every mma half-step drains the previous half's
// accumulator (accX: fills h0/drains h1-same-tile; accY: fills h1/drains
// h0-of-next-tile). 148 blocks x 14-15 tiles, serpentine strip order.

#define NB   4096
#define NN   8192
#define NT   2080
#define NBLK 148
#define C1   2.8853900817779268f   // 2*log2(e)
#define SC   1.69864364f           // sqrt(C1); rows stored pre-scaled
#define LN2  0.69314718055994531f

__device__ __align__(16) unsigned char g_Zb[NN * 256];  // bf16 rows (scaled)
__device__ float g_rowsum[NN];
__device__ float g_self[NN];
__device__ float g_loss;
__device__ unsigned int g_done;

// ---------- helpers ----------
static __device__ __forceinline__ uint32_t smem_u32(const void* p) {
    uint32_t a;
    asm("{ .reg .u64 t; cvta.to.shared.u64 t, %1; cvt.u32.u64 %0, t; }"
        : "=r"(a) : "l"(p));
    return a;
}
#define CP_ASYNC16(dst, src) \
    asm volatile("cp.async.cg.shared.global [%0], [%1], 16;" :: "r"(dst), "l"(src))
#define CP_COMMIT() asm volatile("cp.async.commit_group;")
#define CP_WAIT(n)  asm volatile("cp.async.wait_group %0;" :: "n"(n))

static __device__ __forceinline__ void ldm_x4(uint32_t& r0, uint32_t& r1,
                                              uint32_t& r2, uint32_t& r3,
                                              uint32_t addr) {
    asm volatile("ldmatrix.sync.aligned.m8n8.x4.shared.b16 {%0,%1,%2,%3}, [%4];"
                 : "=r"(r0), "=r"(r1), "=r"(r2), "=r"(r3) : "r"(addr));
}
static __device__ __forceinline__ void mma16816(float* c, const uint32_t* a,
                                                const uint32_t* b) {
    asm volatile(
        "mma.sync.aligned.m16n8k16.row.col.f32.bf16.bf16.f32 "
        "{%0,%1,%2,%3}, {%4,%5,%6,%7}, {%8,%9}, {%0,%1,%2,%3};"
        : "+f"(c[0]), "+f"(c[1]), "+f"(c[2]), "+f"(c[3])
        : "r"(a[0]), "r"(a[1]), "r"(a[2]), "r"(a[3]), "r"(b[0]), "r"(b[1]));
}
static __device__ __forceinline__ float ex2f(float x) {
    float r;
    asm("ex2.approx.f32 %0, %1;" : "=f"(r) : "f"(x));
    return r;
}

// serpentine strip order: pairs (r=p len 64-p, r=63-p len p+1), 65 tiles/pair
static __device__ __forceinline__ void decode(int q, int& r, int& c) {
    int p = q / 65;
    int off = q - p * 65;
    int len1 = 64 - p;
    if (off < len1) { r = p; c = p + off; }
    else            { r = 63 - p; c = r + (off - len1); }
}

static __device__ __forceinline__ void stageP(uint32_t dst, int panel, int tid) {
    const unsigned char* Z = g_Zb;
    #pragma unroll
    for (int i = 0; i < 8; i++) {
        int idx = tid + i * 256;
        int row = idx >> 4, ch = idx & 15;
        uint32_t off = (uint32_t)(row * 256 + ((ch ^ (row & 7)) * 16));
        CP_ASYNC16(dst + off, Z + (size_t)(panel * 128 + row) * 256 + ch * 16);
    }
}

// MMA 32-col half into acc[32], ALWAYS draining epi[32] (4 ex2 per k-step).
static __device__ __forceinline__ void mma_half(
    float* __restrict__ acc, float* __restrict__ epi,
    float* __restrict__ rowacc, float* __restrict__ colacc,
    uint32_t buf, int ncol0, int n_loc, int cpar, const uint32_t (*Ar)[8][4])
{
    #pragma unroll
    for (int f = 0; f < 32; f++) acc[f] = 0.f;
    #pragma unroll
    for (int ks = 0; ks < 8; ks++) {
        uint32_t bfr[8];
        #pragma unroll
        for (int pr = 0; pr < 2; pr++) {
            int n = ncol0 + pr * 16 + n_loc;
            uint32_t addr = buf + (uint32_t)n * 256u
                          + (uint32_t)(((2 * ks + cpar) ^ (n_loc & 7)) * 16);
            ldm_x4(bfr[pr*4+0], bfr[pr*4+1], bfr[pr*4+2], bfr[pr*4+3], addr);
        }
        #pragma unroll
        for (int mi = 0; mi < 2; mi++) {
            mma16816(&acc[mi*16 + 0],  Ar[mi][ks], &bfr[0]);
            mma16816(&acc[mi*16 + 4],  Ar[mi][ks], &bfr[2]);
            mma16816(&acc[mi*16 + 8],  Ar[mi][ks], &bfr[4]);
            mma16816(&acc[mi*16 + 12], Ar[mi][ks], &bfr[6]);
        }
        #pragma unroll
        for (int u = 0; u < 4; u++) {
            int f = ks * 4 + u;
            float e = ex2f(epi[f]);
            rowacc[((f >> 4) << 1) | ((f & 3) >> 1)] += e;
            colacc[(((f >> 2) & 3) << 1) | (f & 1)] += e;
        }
    }
}

static __device__ __forceinline__ void drain32(
    const float* __restrict__ epi, float* __restrict__ rowacc,
    float* __restrict__ colacc)
{
    #pragma unroll
    for (int f = 0; f < 32; f++) {
        float e = ex2f(epi[f]);
        rowacc[((f >> 4) << 1) | ((f & 3) >> 1)] += e;
        colacc[(((f >> 2) & 3) << 1) | (f & 1)] += e;
    }
}

static __device__ __forceinline__ void colflush(float* __restrict__ colacc,
                                                int colbase, int lane) {
    #pragma unroll
    for (int q = 0; q < 8; q++) {
        colacc[q] += __shfl_xor_sync(0xffffffffu, colacc[q], 4);
        colacc[q] += __shfl_xor_sync(0xffffffffu, colacc[q], 8);
        colacc[q] += __shfl_xor_sync(0xffffffffu, colacc[q], 16);
    }
    if (lane < 4) {
        #pragma unroll
        for (int q = 0; q < 8; q++) {
            int col = colbase + (q >> 1) * 8 + 2 * lane + (q & 1);
            atomicAdd(&g_rowsum[col], colacc[q]);
        }
    }
}

static __device__ __forceinline__ void rowflush(float* __restrict__ rowacc,
                                                int rpanel, int wm, int lane) {
    #pragma unroll
    for (int k2 = 0; k2 < 4; k2++) {
        rowacc[k2] += __shfl_xor_sync(0xffffffffu, rowacc[k2], 1);
        rowacc[k2] += __shfl_xor_sync(0xffffffffu, rowacc[k2], 2);
    }
    if ((lane & 3) == 0) {
        int rbase = rpanel * 128 + wm * 32 + (lane >> 2);
        atomicAdd(&g_rowsum[rbase],      rowacc[0]);
        atomicAdd(&g_rowsum[rbase + 8],  rowacc[1]);
        atomicAdd(&g_rowsum[rbase + 16], rowacc[2]);
        atomicAdd(&g_rowsum[rbase + 24], rowacc[3]);
    }
}

// ---------- kernels ----------
__global__ void norm_kernel(const float* __restrict__ zi,
                            const float* __restrict__ zj) {
    int gt = blockIdx.x * blockDim.x + threadIdx.x;
    if (gt < NN) g_rowsum[gt] = 0.f;
    if (gt == 0) { g_loss = 0.f; g_done = 0u; }
    int row = gt >> 5;
    int lane = threadIdx.x & 31;
    if (row >= NN) return;
    const float* src = (row < NB) ? (zi + (size_t)row * 128)
                                  : (zj + (size_t)(row - NB) * 128);
    float4 v = ((const float4*)src)[lane];
    float ss = v.x*v.x + v.y*v.y + v.z*v.z + v.w*v.w;
    #pragma unroll
    for (int o = 16; o; o >>= 1) ss += __shfl_xor_sync(0xffffffffu, ss, o);
    float sca = SC / fmaxf(sqrtf(ss), 1e-12f);
    __nv_bfloat162 p0 = __floats2bfloat162_rn(v.x * sca, v.y * sca);
    __nv_bfloat162 p1 = __floats2bfloat162_rn(v.z * sca, v.w * sca);
    float2 q0 = __bfloat1622float2(p0);
    float2 q1 = __bfloat1622float2(p1);
    float sd = q0.x*q0.x + q0.y*q0.y + q1.x*q1.x + q1.y*q1.y;
    #pragma unroll
    for (int o = 16; o; o >>= 1) sd += __shfl_xor_sync(0xffffffffu, sd, o);
    if (lane == 0) g_self[row] = sd;
    uint2 pk;
    pk.x = *reinterpret_cast<uint32_t*>(&p0);
    pk.y = *reinterpret_cast<uint32_t*>(&p1);
    *reinterpret_cast<uint2*>(g_Zb + (size_t)row * 256 + lane * 8) = pk;
}

__global__ void __launch_bounds__(256, 1) sim_kernel() {
    extern __shared__ unsigned char smraw[];
    uint32_t s0 = smem_u32(smraw);
    uint32_t Abuf[2] = { s0, s0 + 32768u };
    uint32_t Bbuf[2] = { s0 + 65536u, s0 + 98304u };

    int tid = threadIdx.x, lane = tid & 31, w = tid >> 5;
    int wm = w & 3, wn = w >> 2;
    int b = blockIdx.x;
    int cnt = 14 + (b < 8 ? 1 : 0);
    int q0 = b * 14 + (b < 8 ? b : 8);

    int n_loc = (lane & 7) + ((lane >> 4) << 3);
    int cpar = (lane >> 3) & 1;
    int row_loc = (lane & 7) + ((lane >> 3) & 1) * 8;
    int kpar = (lane >> 4) & 1;

    // prologue staging
    int r0p, c0p, r1p, c1p;
    decode(q0, r0p, c0p);
    decode(q0 + 1, r1p, c1p);
    stageP(Abuf[0], r0p, tid);
    stageP(Bbuf[0], c0p, tid);
    CP_COMMIT();
    int stgA = 1;
    if (r1p != r0p) { stageP(Abuf[1], r1p, tid); stgA = 0; }
    stageP(Bbuf[1], c1p, tid);
    CP_COMMIT();

    uint32_t Ar[2][8][4];
    float rowacc[4], colacc[8];
    float accX[32], accY[32];
    #pragma unroll
    for (int f = 0; f < 32; f++) accY[f] = -__int_as_float(0x7f800000); // -inf
    #pragma unroll
    for (int k2 = 0; k2 < 4; k2++) rowacc[k2] = 0.f;
    #pragma unroll
    for (int k2 = 0; k2 < 8; k2++) colacc[k2] = 0.f;

    int useA = 0, rprev = -1;
    int rpt = -1, cpt = -1;               // previous tile's (r, c)
    int nbase = wn * 64;

    for (int t = 0; t < cnt; t++) {
        int q = q0 + t;
        int r, c;
        decode(q, r, c);
        int buf = t & 1;

        CP_WAIT(1);
        __syncthreads();

        if (r != rprev) {
            if (t > 0) useA ^= 1;
            uint32_t abase = Abuf[useA] + (uint32_t)(wm * 32 + row_loc) * 256u;
            #pragma unroll
            for (int ma = 0; ma < 2; ma++)
                #pragma unroll
                for (int ks = 0; ks < 8; ks++) {
                    uint32_t addr = abase + (uint32_t)(ma * 16) * 256u
                                  + (uint32_t)(((2 * ks + kpar) ^ (row_loc & 7)) * 16);
                    ldm_x4(Ar[ma][ks][0], Ar[ma][ks][1], Ar[ma][ks][2], Ar[ma][ks][3], addr);
                }
        }
        rprev = r;

        // h0: fill accX, drain accY = h1 of previous tile
        mma_half(accX, accY, rowacc, colacc, Bbuf[buf], nbase, n_loc, cpar, Ar);
        if (t > 0) {                      // flush previous tile's accumulations
            if (rpt != cpt) colflush(colacc, cpt * 128 + nbase + 32, lane);
            rowflush(rowacc, rpt, wm, lane);
            #pragma unroll
            for (int k2 = 0; k2 < 4; k2++) rowacc[k2] = 0.f;
            #pragma unroll
            for (int k2 = 0; k2 < 8; k2++) colacc[k2] = 0.f;
        }
        // h1: fill accY, drain accX = h0 of current tile
        mma_half(accY, accX, rowacc, colacc, Bbuf[buf], nbase + 32, n_loc, cpar, Ar);
        if (r != c) colflush(colacc, c * 128 + nbase, lane);
        #pragma unroll
        for (int k2 = 0; k2 < 8; k2++) colacc[k2] = 0.f;

        __syncthreads();                  // all warps done with Bbuf[buf]
        if (t + 2 < cnt) {
            int r2, c2, rn, cn;
            decode(q + 2, r2, c2);
            decode(q + 1, rn, cn);
            stageP(Bbuf[buf], c2, tid);
            if (r2 != rn) { stageP(Abuf[stgA], r2, tid); stgA ^= 1; }
        }
        CP_COMMIT();
        rpt = r; cpt = c;
    }

    // epilogue: drain last tile's h1
    drain32(accY, rowacc, colacc);
    if (rpt != cpt) colflush(colacc, cpt * 128 + nbase + 32, lane);
    rowflush(rowacc, rpt, wm, lane);
}

// one warp per positive pair (p, p+NB)
__global__ void finish_kernel(float* __restrict__ out) {
    __shared__ float sh[8];
    int tid = threadIdx.x, lane = tid & 31, w = tid >> 5;
    int p = blockIdx.x * 8 + w;
    int q = p + NB;
    uint2 ua = *reinterpret_cast<const uint2*>(g_Zb + (size_t)p * 256 + lane * 8);
    uint2 ub = *reinterpret_cast<const uint2*>(g_Zb + (size_t)q * 256 + lane * 8);
    float2 a0 = __bfloat1622float2(*reinterpret_cast<__nv_bfloat162*>(&ua.x));
    float2 a1 = __bfloat1622float2(*reinterpret_cast<__nv_bfloat162*>(&ua.y));
    float2 b0 = __bfloat1622float2(*reinterpret_cast<__nv_bfloat162*>(&ub.x));
    float2 b1 = __bfloat1622float2(*reinterpret_cast<__nv_bfloat162*>(&ub.y));
    float pd = a0.x*b0.x + a0.y*b0.y + a1.x*b1.x + a1.y*b1.y;
    #pragma unroll
    for (int o = 16; o; o >>= 1) pd += __shfl_xor_sync(0xffffffffu, pd, o);
    if (lane == 0) {
        float rsp = g_rowsum[p] - ex2f(g_self[p]);
        float rsq = g_rowsum[q] - ex2f(g_self[q]);
        sh[w] = logf(rsp) + logf(rsq) - 2.0f * LN2 * pd;
    }
    __syncthreads();
    if (tid == 0) {
        float t = 0.f;
        #pragma unroll
        for (int kk = 0; kk < 8; kk++) t += sh[kk];
        atomicAdd(&g_loss, t);
        __threadfence();
        unsigned int done = atomicAdd(&g_done, 1u);
        if (done == (unsigned int)(gridDim.x - 1)) {
            out[0] = g_loss * (1.0f / (float)NN);
        }
    }
}

extern "C" void kernel_launch(void* const* d_in, const int* in_sizes, int n_in,
                              void* d_out, int out_size) {
    const float* zi = (const float*)d_in[0];
    const float* zj = (const float*)d_in[1];
    float* out = (float*)d_out;
    (void)in_sizes; (void)n_in; (void)out_size;

    (void)cudaFuncSetAttribute(sim_kernel,
                               cudaFuncAttributeMaxDynamicSharedMemorySize,
                               131072);

    norm_kernel<<<1024, 256>>>(zi, zj);
    sim_kernel<<<NBLK, 256, 131072>>>();
    finish_kernel<<<NB / 8, 256>>>(out);
}

// round 17
// speedup vs baseline: 1.1404x; 1.0287x over previous
#include <cuda_runtime.h>
#include <cuda_bf16.h>
#include <cstdint>
#include <math.h>

// NT-Xent loss, B=4096, D=128, N=8192, T=0.5 — mma.sync bf16, SYMMETRIC v4
// R16: 3 kernels again (fused-barrier version regressed); sim epilogue fully
// pipelined ACROSS tiles: every mma half-step drains the previous half's
// accumulator (accX: fills h0/drains h1-same-tile; accY: fills h1/drains
// h0-of-next-tile). 148 blocks x 14-15 tiles, serpentine strip order.

#define NB   4096
#define NN   8192
#define NT   2080
#define NBLK 148
#define C1   2.8853900817779268f   // 2*log2(e)
#define SC   1.69864364f           // sqrt(C1); rows stored pre-scaled
#define LN2  0.69314718055994531f

__device__ __align__(16) unsigned char g_Zb[NN * 256];  // bf16 rows (scaled)
__device__ float g_rowsum[NN];
__device__ float g_self[NN];
__device__ float g_loss;
__device__ unsigned int g_done;

// ---------- helpers ----------
static __device__ __forceinline__ uint32_t smem_u32(const void* p) {
    uint32_t a;
    asm("{ .reg .u64 t; cvta.to.shared.u64 t, %1; cvt.u32.u64 %0, t; }"
        : "=r"(a) : "l"(p));
    return a;
}
#define CP_ASYNC16(dst, src) \
    asm volatile("cp.async.cg.shared.global [%0], [%1], 16;" :: "r"(dst), "l"(src))
#define CP_COMMIT() asm volatile("cp.async.commit_group;")
#define CP_WAIT(n)  asm volatile("cp.async.wait_group %0;" :: "n"(n))

static __device__ __forceinline__ void ldm_x4(uint32_t& r0, uint32_t& r1,
                                              uint32_t& r2, uint32_t& r3,
                                              uint32_t addr) {
    asm volatile("ldmatrix.sync.aligned.m8n8.x4.shared.b16 {%0,%1,%2,%3}, [%4];"
                 : "=r"(r0), "=r"(r1), "=r"(r2), "=r"(r3) : "r"(addr));
}
static __device__ __forceinline__ void mma16816(float* c, const uint32_t* a,
                                                const uint32_t* b) {
    asm volatile(
        "mma.sync.aligned.m16n8k16.row.col.f32.bf16.bf16.f32 "
        "{%0,%1,%2,%3}, {%4,%5,%6,%7}, {%8,%9}, {%0,%1,%2,%3};"
        : "+f"(c[0]), "+f"(c[1]), "+f"(c[2]), "+f"(c[3])
        : "r"(a[0]), "r"(a[1]), "r"(a[2]), "r"(a[3]), "r"(b[0]), "r"(b[1]));
}
static __device__ __forceinline__ float ex2f(float x) {
    float r;
    asm("ex2.approx.f32 %0, %1;" : "=f"(r) : "f"(x));
    return r;
}

// serpentine strip order: pairs (r=p len 64-p, r=63-p len p+1), 65 tiles/pair
static __device__ __forceinline__ void decode(int q, int& r, int& c) {
    int p = q / 65;
    int off = q - p * 65;
    int len1 = 64 - p;
    if (off < len1) { r = p; c = p + off; }
    else            { r = 63 - p; c = r + (off - len1); }
}

static __device__ __forceinline__ void stageP(uint32_t dst, int panel, int tid) {
    const unsigned char* Z = g_Zb;
    #pragma unroll
    for (int i = 0; i < 8; i++) {
        int idx = tid + i * 256;
        int row = idx >> 4, ch = idx & 15;
        uint32_t off = (uint32_t)(row * 256 + ((ch ^ (row & 7)) * 16));
        CP_ASYNC16(dst + off, Z + (size_t)(panel * 128 + row) * 256 + ch * 16);
    }
}

// MMA 32-col half into acc[32], ALWAYS draining epi[32] (4 ex2 per k-step).
static __device__ __forceinline__ void mma_half(
    float* __restrict__ acc, float* __restrict__ epi,
    float* __restrict__ rowacc, float* __restrict__ colacc,
    uint32_t buf, int ncol0, int n_loc, int cpar, const uint32_t (*Ar)[8][4])
{
    #pragma unroll
    for (int f = 0; f < 32; f++) acc[f] = 0.f;
    #pragma unroll
    for (int ks = 0; ks < 8; ks++) {
        uint32_t bfr[8];
        #pragma unroll
        for (int pr = 0; pr < 2; pr++) {
            int n = ncol0 + pr * 16 + n_loc;
            uint32_t addr = buf + (uint32_t)n * 256u
                          + (uint32_t)(((2 * ks + cpar) ^ (n_loc & 7)) * 16);
            ldm_x4(bfr[pr*4+0], bfr[pr*4+1], bfr[pr*4+2], bfr[pr*4+3], addr);
        }
        #pragma unroll
        for (int mi = 0; mi < 2; mi++) {
            mma16816(&acc[mi*16 + 0],  Ar[mi][ks], &bfr[0]);
            mma16816(&acc[mi*16 + 4],  Ar[mi][ks], &bfr[2]);
            mma16816(&acc[mi*16 + 8],  Ar[mi][ks], &bfr[4]);
            mma16816(&acc[mi*16 + 12], Ar[mi][ks], &bfr[6]);
        }
        #pragma unroll
        for (int u = 0; u < 4; u++) {
            int f = ks * 4 + u;
            float e = ex2f(epi[f]);
            rowacc[((f >> 4) << 1) | ((f & 3) >> 1)] += e;
            colacc[(((f >> 2) & 3) << 1) | (f & 1)] += e;
        }
    }
}

static __device__ __forceinline__ void drain32(
    const float* __restrict__ epi, float* __restrict__ rowacc,
    float* __restrict__ colacc)
{
    #pragma unroll
    for (int f = 0; f < 32; f++) {
        float e = ex2f(epi[f]);
        rowacc[((f >> 4) << 1) | ((f & 3) >> 1)] += e;
        colacc[(((f >> 2) & 3) << 1) | (f & 1)] += e;
    }
}

static __device__ __forceinline__ void colflush(float* __restrict__ colacc,
                                                int colbase, int lane) {
    #pragma unroll
    for (int q = 0; q < 8; q++) {
        colacc[q] += __shfl_xor_sync(0xffffffffu, colacc[q], 4);
        colacc[q] += __shfl_xor_sync(0xffffffffu, colacc[q], 8);
        colacc[q] += __shfl_xor_sync(0xffffffffu, colacc[q], 16);
    }
    if (lane < 4) {
        #pragma unroll
        for (int q = 0; q < 8; q++) {
            int col = colbase + (q >> 1) * 8 + 2 * lane + (q & 1);
            atomicAdd(&g_rowsum[col], colacc[q]);
        }
    }
}

static __device__ __forceinline__ void rowflush(float* __restrict__ rowacc,
                                                int rpanel, int wm, int lane) {
    #pragma unroll
    for (int k2 = 0; k2 < 4; k2++) {
        rowacc[k2] += __shfl_xor_sync(0xffffffffu, rowacc[k2], 1);
        rowacc[k2] += __shfl_xor_sync(0xffffffffu, rowacc[k2], 2);
    }
    if ((lane & 3) == 0) {
        int rbase = rpanel * 128 + wm * 32 + (lane >> 2);
        atomicAdd(&g_rowsum[rbase],      rowacc[0]);
        atomicAdd(&g_rowsum[rbase + 8],  rowacc[1]);
        atomicAdd(&g_rowsum[rbase + 16], rowacc[2]);
        atomicAdd(&g_rowsum[rbase + 24], rowacc[3]);
    }
}

// ---------- kernels ----------
__global__ void norm_kernel(const float* __restrict__ zi,
                            const float* __restrict__ zj) {
    int gt = blockIdx.x * blockDim.x + threadIdx.x;
    if (gt < NN) g_rowsum[gt] = 0.f;
    if (gt == 0) { g_loss = 0.f; g_done = 0u; }
    int row = gt >> 5;
    int lane = threadIdx.x & 31;
    if (row >= NN) return;
    const float* src = (row < NB) ? (zi + (size_t)row * 128)
                                  : (zj + (size_t)(row - NB) * 128);
    float4 v = ((const float4*)src)[lane];
    float ss = v.x*v.x + v.y*v.y + v.z*v.z + v.w*v.w;
    #pragma unroll
    for (int o = 16; o; o >>= 1) ss += __shfl_xor_sync(0xffffffffu, ss, o);
    float sca = SC / fmaxf(sqrtf(ss), 1e-12f);
    __nv_bfloat162 p0 = __floats2bfloat162_rn(v.x * sca, v.y * sca);
    __nv_bfloat162 p1 = __floats2bfloat162_rn(v.z * sca, v.w * sca);
    float2 q0 = __bfloat1622float2(p0);
    float2 q1 = __bfloat1622float2(p1);
    float sd = q0.x*q0.x + q0.y*q0.y + q1.x*q1.x + q1.y*q1.y;
    #pragma unroll
    for (int o = 16; o; o >>= 1) sd += __shfl_xor_sync(0xffffffffu, sd, o);
    if (lane == 0) g_self[row] = sd;
    uint2 pk;
    pk.x = *reinterpret_cast<uint32_t*>(&p0);
    pk.y = *reinterpret_cast<uint32_t*>(&p1);
    *reinterpret_cast<uint2*>(g_Zb + (size_t)row * 256 + lane * 8) = pk;
}

__global__ void __launch_bounds__(256, 1) sim_kernel() {
    extern __shared__ unsigned char smraw[];
    uint32_t s0 = smem_u32(smraw);
    uint32_t Abuf[2] = { s0, s0 + 32768u };
    uint32_t Bbuf[2] = { s0 + 65536u, s0 + 98304u };

    int tid = threadIdx.x, lane = tid & 31, w = tid >> 5;
    int wm = w & 3, wn = w >> 2;
    int b = blockIdx.x;
    int cnt = 14 + (b < 8 ? 1 : 0);
    int q0 = b * 14 + (b < 8 ? b : 8);

    int n_loc = (lane & 7) + ((lane >> 4) << 3);
    int cpar = (lane >> 3) & 1;
    int row_loc = (lane & 7) + ((lane >> 3) & 1) * 8;
    int kpar = (lane >> 4) & 1;

    // prologue staging
    int r0p, c0p, r1p, c1p;
    decode(q0, r0p, c0p);
    decode(q0 + 1, r1p, c1p);
    stageP(Abuf[0], r0p, tid);
    stageP(Bbuf[0], c0p, tid);
    CP_COMMIT();
    int stgA = 1;
    if (r1p != r0p) { stageP(Abuf[1], r1p, tid); stgA = 0; }
    stageP(Bbuf[1], c1p, tid);
    CP_COMMIT();

    uint32_t Ar[2][8][4];
    float rowacc[4], colacc[8];
    float accX[32], accY[32];
    #pragma unroll
    for (int f = 0; f < 32; f++) accY[f] = -__int_as_float(0x7f800000); // -inf
    #pragma unroll
    for (int k2 = 0; k2 < 4; k2++) rowacc[k2] = 0.f;
    #pragma unroll
    for (int k2 = 0; k2 < 8; k2++) colacc[k2] = 0.f;

    int useA = 0, rprev = -1;
    int rpt = -1, cpt = -1;               // previous tile's (r, c)
    int nbase = wn * 64;

    for (int t = 0; t < cnt; t++) {
        int q = q0 + t;
        int r, c;
        decode(q, r, c);
        int buf = t & 1;

        CP_WAIT(1);
        __syncthreads();

        if (r != rprev) {
            if (t > 0) useA ^= 1;
            uint32_t abase = Abuf[useA] + (uint32_t)(wm * 32 + row_loc) * 256u;
            #pragma unroll
            for (int ma = 0; ma < 2; ma++)
                #pragma unroll
                for (int ks = 0; ks < 8; ks++) {
                    uint32_t addr = abase + (uint32_t)(ma * 16) * 256u
                                  + (uint32_t)(((2 * ks + kpar) ^ (row_loc & 7)) * 16);
                    ldm_x4(Ar[ma][ks][0], Ar[ma][ks][1], Ar[ma][ks][2], Ar[ma][ks][3], addr);
                }
        }
        rprev = r;

        // h0: fill accX, drain accY = h1 of previous tile
        mma_half(accX, accY, rowacc, colacc, Bbuf[buf], nbase, n_loc, cpar, Ar);
        if (t > 0) {                      // flush previous tile's accumulations
            if (rpt != cpt) colflush(colacc, cpt * 128 + nbase + 32, lane);
            rowflush(rowacc, rpt, wm, lane);
            #pragma unroll
            for (int k2 = 0; k2 < 4; k2++) rowacc[k2] = 0.f;
            #pragma unroll
            for (int k2 = 0; k2 < 8; k2++) colacc[k2] = 0.f;
        }
        // h1: fill accY, drain accX = h0 of current tile
        mma_half(accY, accX, rowacc, colacc, Bbuf[buf], nbase + 32, n_loc, cpar, Ar);
        if (r != c) colflush(colacc, c * 128 + nbase, lane);
        #pragma unroll
        for (int k2 = 0; k2 < 8; k2++) colacc[k2] = 0.f;

        __syncthreads();                  // all warps done with Bbuf[buf]
        if (t + 2 < cnt) {
            int r2, c2, rn, cn;
            decode(q + 2, r2, c2);
            decode(q + 1, rn, cn);
            stageP(Bbuf[buf], c2, tid);
            if (r2 != rn) { stageP(Abuf[stgA], r2, tid); stgA ^= 1; }
        }
        CP_COMMIT();
        rpt = r; cpt = c;
    }

    // epilogue: drain last tile's h1
    drain32(accY, rowacc, colacc);
    if (rpt != cpt) colflush(colacc, cpt * 128 + nbase + 32, lane);
    rowflush(rowacc, rpt, wm, lane);
}

// one warp per positive pair (p, p+NB)
__global__ void finish_kernel(float* __restrict__ out) {
    __shared__ float sh[8];
    int tid = threadIdx.x, lane = tid & 31, w = tid >> 5;
    int p = blockIdx.x * 8 + w;
    int q = p + NB;
    uint2 ua = *reinterpret_cast<const uint2*>(g_Zb + (size_t)p * 256 + lane * 8);
    uint2 ub = *reinterpret_cast<const uint2*>(g_Zb + (size_t)q * 256 + lane * 8);
    float2 a0 = __bfloat1622float2(*reinterpret_cast<__nv_bfloat162*>(&ua.x));
    float2 a1 = __bfloat1622float2(*reinterpret_cast<__nv_bfloat162*>(&ua.y));
    float2 b0 = __bfloat1622float2(*reinterpret_cast<__nv_bfloat162*>(&ub.x));
    float2 b1 = __bfloat1622float2(*reinterpret_cast<__nv_bfloat162*>(&ub.y));
    float pd = a0.x*b0.x + a0.y*b0.y + a1.x*b1.x + a1.y*b1.y;
    #pragma unroll
    for (int o = 16; o; o >>= 1) pd += __shfl_xor_sync(0xffffffffu, pd, o);
    if (lane == 0) {
        float rsp = g_rowsum[p] - ex2f(g_self[p]);
        float rsq = g_rowsum[q] - ex2f(g_self[q]);
        sh[w] = logf(rsp) + logf(rsq) - 2.0f * LN2 * pd;
    }
    __syncthreads();
    if (tid == 0) {
        float t = 0.f;
        #pragma unroll
        for (int kk = 0; kk < 8; kk++) t += sh[kk];
        atomicAdd(&g_loss, t);
        __threadfence();
        unsigned int done = atomicAdd(&g_done, 1u);
        if (done == (unsigned int)(gridDim.x - 1)) {
            out[0] = g_loss * (1.0f / (float)NN);
        }
    }
}

extern "C" void kernel_launch(void* const* d_in, const int* in_sizes, int n_in,
                              void* d_out, int out_size) {
    const float* zi = (const float*)d_in[0];
    const float* zj = (const float*)d_in[1];
    float* out = (float*)d_out;
    (void)in_sizes; (void)n_in; (void)out_size;

    (void)cudaFuncSetAttribute(sim_kernel,
                               cudaFuncAttributeMaxDynamicSharedMemorySize,
                               131072);

    norm_kernel<<<1024, 256>>>(zi, zj);
    sim_kernel<<<NBLK, 256, 131072>>>();
    finish_kernel<<<NB / 8, 256>>>(out);
}